// round 11
// baseline (speedup 1.0000x reference)
#include <cuda_runtime.h>
#include <math.h>

#define Cc 64
#define Hh 192
#define Ww 192
#define HW (Hh*Ww)            // 36864
#define Bb 4
#define NPIX (Bb*HW)          // 147456
#define NTOT (Bb*Cc*HW)       // 9437184
#define NSPLIT 36
#define HEADS 2

typedef unsigned long long u64c;

// ---------------- scratch (static device memory; no allocs) ----------------
__device__ float g_bufA[NTOT];
__device__ float g_bufB[NTOT];
__device__ float g_bufC[NTOT];   // x1 (kept)
__device__ float g_bufD[NTOT];
__device__ float g_bufE[NTOT];   // out1 (kept)
__device__ float g_bufF[NTOT];   // out2
__device__ float g_bufG[NTOT];   // out3 / x1_t
__device__ float g_bufH[NTOT];   // out1_t / out3_t
__device__ float g_invQ[Bb*Cc];
__device__ float g_invK[Bb*Cc];
__device__ float g_attn[Bb*HEADS*32*32];
__device__ float g_M[Bb*Cc*Cc];

__device__ __forceinline__ float gelu_erf(float v){
    return 0.5f*v*(1.f+erff(v*0.70710678118654752f));
}
__device__ __forceinline__ u64c pack2(float lo, float hi){
    u64c r; asm("mov.b64 %0, {%1, %2};" : "=l"(r) : "f"(lo), "f"(hi)); return r;
}
__device__ __forceinline__ u64c ffma2(u64c a, u64c b, u64c c){
    u64c d; asm("fma.rn.f32x2 %0, %1, %2, %3;" : "=l"(d) : "l"(a), "l"(b), "l"(c)); return d;
}
__device__ __forceinline__ float2 unpack2(u64c v){
    float2 f; asm("mov.b64 {%0, %1}, %2;" : "=f"(f.x), "=f"(f.y) : "l"(v)); return f;
}

// ulonglong2 = 16 bytes = 4 floats. Channel stride HW floats = HW/4 ulonglong2.
#define CH_STRIDE_U2 (HW/4)

// ============= 1x1 conv (no bias), f32x2, occupancy-tiled =============
// thread: 4 pixels x 8 outputs (32 acc regs). block: 256 thr = 128 px x 64 out.
__global__ void __launch_bounds__(256, 3)
conv1x1_nb(const float* __restrict__ x, const float* __restrict__ w,
           float* __restrict__ y){
    __shared__ u64c ws[64*64];  // ws[c*64+o] = {w[o][c], w[o][c]}  (32KB)
    for (int idx = threadIdx.x; idx < 4096; idx += 256){
        int o = idx >> 6, c = idx & 63;
        float wv = w[idx];
        ws[c*64 + o] = pack2(wv, wv);
    }
    __syncthreads();
    int pg = threadIdx.x & 31, og = threadIdx.x >> 5;   // og 0..7
    int blockPix = blockIdx.x * 128;
    int b = blockPix / HW;
    int n0 = blockPix - b*HW + pg*4;
    const ulonglong2* xb = (const ulonglong2*)(x + (size_t)b*Cc*HW + n0);
    u64c acc[8][2];
    #pragma unroll
    for (int i=0;i<8;i++){ acc[i][0]=0ull; acc[i][1]=0ull; }
    #pragma unroll 4
    for (int c=0;c<64;c++){
        ulonglong2 xv = xb[(size_t)c*CH_STRIDE_U2];      // 4 pixels
        const ulonglong2* wr = (const ulonglong2*)(ws + c*64 + og*8);
        #pragma unroll
        for (int k=0;k<4;k++){
            ulonglong2 wp = wr[k];                       // broadcast LDS.128
            acc[2*k  ][0] = ffma2(wp.x, xv.x, acc[2*k  ][0]);
            acc[2*k  ][1] = ffma2(wp.x, xv.y, acc[2*k  ][1]);
            acc[2*k+1][0] = ffma2(wp.y, xv.x, acc[2*k+1][0]);
            acc[2*k+1][1] = ffma2(wp.y, xv.y, acc[2*k+1][1]);
        }
    }
    ulonglong2* yb = (ulonglong2*)(y + (size_t)b*Cc*HW + n0);
    #pragma unroll
    for (int i=0;i<8;i++){
        ulonglong2 v; v.x = acc[i][0]; v.y = acc[i][1];
        yb[(size_t)(og*8+i)*CH_STRIDE_U2] = v;
    }
}

// ============= same, per-batch weights (channel-attn out1 = M_b @ V) =============
__global__ void __launch_bounds__(256, 3)
conv1x1_batch(const float* __restrict__ x, const float* __restrict__ wAll,
              float* __restrict__ y){
    __shared__ u64c ws[64*64];
    int blockPix = blockIdx.x * 128;
    int b = blockPix / HW;
    const float* w = wAll + (size_t)b*4096;
    for (int idx = threadIdx.x; idx < 4096; idx += 256){
        int o = idx >> 6, c = idx & 63;
        float wv = w[idx];
        ws[c*64 + o] = pack2(wv, wv);
    }
    __syncthreads();
    int pg = threadIdx.x & 31, og = threadIdx.x >> 5;
    int n0 = blockPix - b*HW + pg*4;
    const ulonglong2* xb = (const ulonglong2*)(x + (size_t)b*Cc*HW + n0);
    u64c acc[8][2];
    #pragma unroll
    for (int i=0;i<8;i++){ acc[i][0]=0ull; acc[i][1]=0ull; }
    #pragma unroll 4
    for (int c=0;c<64;c++){
        ulonglong2 xv = xb[(size_t)c*CH_STRIDE_U2];
        const ulonglong2* wr = (const ulonglong2*)(ws + c*64 + og*8);
        #pragma unroll
        for (int k=0;k<4;k++){
            ulonglong2 wp = wr[k];
            acc[2*k  ][0] = ffma2(wp.x, xv.x, acc[2*k  ][0]);
            acc[2*k  ][1] = ffma2(wp.x, xv.y, acc[2*k  ][1]);
            acc[2*k+1][0] = ffma2(wp.y, xv.x, acc[2*k+1][0]);
            acc[2*k+1][1] = ffma2(wp.y, xv.y, acc[2*k+1][1]);
        }
    }
    ulonglong2* yb = (ulonglong2*)(y + (size_t)b*Cc*HW + n0);
    #pragma unroll
    for (int i=0;i<8;i++){
        ulonglong2 v; v.x = acc[i][0]; v.y = acc[i][1];
        yb[(size_t)(og*8+i)*CH_STRIDE_U2] = v;
    }
}

// ============= HW transpose: [b,c,h,w] -> [b,c,w,h], 32x32 smem tiles =============
__global__ void __launch_bounds__(256)
transpose_hw(const float* __restrict__ in, float* __restrict__ out){
    __shared__ float tile[32][33];
    int plane = blockIdx.x;                 // b*Cc + c
    int th = (blockIdx.y / 6) * 32;
    int tw = (blockIdx.y % 6) * 32;
    size_t basep = (size_t)plane * HW;
    int tx = threadIdx.x & 31, ty4 = (threadIdx.x >> 5) * 4;
    #pragma unroll
    for (int r=0;r<4;r++)
        tile[ty4+r][tx] = in[basep + (size_t)(th+ty4+r)*Ww + tw + tx];
    __syncthreads();
    #pragma unroll
    for (int r=0;r<4;r++)
        out[basep + (size_t)(tw+ty4+r)*Hh + th + tx] = tile[tx][ty4+r];
}

// ============= depthwise 3x3 + bias, fused GELU =============
__global__ void dwconv(const float* __restrict__ x, const float* __restrict__ w,
                       const float* __restrict__ bias, float* __restrict__ y){
    int idx = blockIdx.x*256 + threadIdx.x;
    if (idx >= NTOT) return;
    int n  = idx % HW;
    int bc = idx / HW;
    int c  = bc & 63;
    int h = n / Ww, wc = n - h*Ww;
    const float* wp = w + c*9;
    float acc = bias[c];
    #pragma unroll
    for (int dy=-1;dy<=1;dy++){
        int hh = h + dy;
        if (hh < 0 || hh >= Hh) continue;
        #pragma unroll
        for (int dx=-1;dx<=1;dx++){
            int ww2 = wc + dx;
            if (ww2 < 0 || ww2 >= Ww) continue;
            acc += wp[(dy+1)*3 + (dx+1)] * x[idx + dy*Ww + dx];
        }
    }
    y[idx] = gelu_erf(acc);
}

// ============= x1 = conv2(g) + b2 + conv0(x) + b0, g already gelu'd, f32x2 =============
__global__ void __launch_bounds__(256, 2)
x1_fuse(const float* __restrict__ g, const float* __restrict__ x,
        const float* __restrict__ w2, const float* __restrict__ b2,
        const float* __restrict__ w0, const float* __restrict__ b0,
        float* __restrict__ y){
    extern __shared__ u64c sm2[];
    u64c* ws2 = sm2;          // 32KB
    u64c* ws0 = sm2 + 4096;   // 32KB
    for (int idx = threadIdx.x; idx < 4096; idx += 256){
        int o = idx >> 6, c = idx & 63;
        float a2 = w2[idx], a0 = w0[idx];
        ws2[c*64+o] = pack2(a2, a2);
        ws0[c*64+o] = pack2(a0, a0);
    }
    __syncthreads();
    int pg = threadIdx.x & 63, og = threadIdx.x >> 6;
    int blockPix = blockIdx.x * 256;
    int b = blockPix / HW;
    int n0 = blockPix - b*HW + pg*4;
    const ulonglong2* gb = (const ulonglong2*)(g + (size_t)b*Cc*HW + n0);
    const ulonglong2* xb = (const ulonglong2*)(x + (size_t)b*Cc*HW + n0);
    u64c acc[16][2];
    #pragma unroll
    for (int i=0;i<16;i++){
        float bv = b2[og*16+i] + b0[og*16+i];
        u64c p = pack2(bv,bv);
        acc[i][0]=p; acc[i][1]=p;
    }
    #pragma unroll 2
    for (int c=0;c<64;c++){
        ulonglong2 gv = gb[(size_t)c*CH_STRIDE_U2];
        ulonglong2 xv = xb[(size_t)c*CH_STRIDE_U2];
        const ulonglong2* w2r = (const ulonglong2*)(ws2 + c*64 + og*16);
        const ulonglong2* w0r = (const ulonglong2*)(ws0 + c*64 + og*16);
        #pragma unroll
        for (int k=0;k<8;k++){
            ulonglong2 a2 = w2r[k], a0 = w0r[k];
            acc[2*k  ][0] = ffma2(a2.x, gv.x, acc[2*k  ][0]);
            acc[2*k  ][1] = ffma2(a2.x, gv.y, acc[2*k  ][1]);
            acc[2*k+1][0] = ffma2(a2.y, gv.x, acc[2*k+1][0]);
            acc[2*k+1][1] = ffma2(a2.y, gv.y, acc[2*k+1][1]);
            acc[2*k  ][0] = ffma2(a0.x, xv.x, acc[2*k  ][0]);
            acc[2*k  ][1] = ffma2(a0.x, xv.y, acc[2*k  ][1]);
            acc[2*k+1][0] = ffma2(a0.y, xv.x, acc[2*k+1][0]);
            acc[2*k+1][1] = ffma2(a0.y, xv.y, acc[2*k+1][1]);
        }
    }
    ulonglong2* yb = (ulonglong2*)(y + (size_t)b*Cc*HW + n0);
    #pragma unroll
    for (int i=0;i<16;i++){
        ulonglong2 v; v.x = acc[i][0]; v.y = acc[i][1];
        yb[(size_t)(og*16+i)*CH_STRIDE_U2] = v;
    }
}

// ---------------- per-(b,channel) 1/max(||.||,1e-12) over HW, for Q and K
__global__ void norm_kernel(const float* __restrict__ Q, const float* __restrict__ K,
                            float* __restrict__ invQ, float* __restrict__ invK){
    const float* src = blockIdx.y ? K : Q;
    size_t base = (size_t)blockIdx.x * HW;
    float s = 0.f;
    for (int i = threadIdx.x; i < HW/4; i += 256){
        float4 v = ((const float4*)(src + base))[i];
        s += v.x*v.x + v.y*v.y + v.z*v.z + v.w*v.w;
    }
    #pragma unroll
    for (int o=16;o;o>>=1) s += __shfl_xor_sync(0xffffffffu, s, o);
    __shared__ float red[8];
    int warp = threadIdx.x >> 5, lane = threadIdx.x & 31;
    if (lane == 0) red[warp] = s;
    __syncthreads();
    if (threadIdx.x == 0){
        float t = 0.f;
        #pragma unroll
        for (int i=0;i<8;i++) t += red[i];
        float inv = 1.f / fmaxf(sqrtf(t), 1e-12f);
        (blockIdx.y ? invK : invQ)[blockIdx.x] = inv;
    }
}

__global__ void zero_attn(float* __restrict__ a){
    int i = blockIdx.x*256 + threadIdx.x;
    if (i < Bb*HEADS*32*32) a[i] = 0.f;
}

// ---------------- attn_raw[bg,c,d] += sum_n Q[c,n]K[d,n] over an n-chunk
__global__ void attn_dot(const float* __restrict__ Q, const float* __restrict__ K,
                         float* __restrict__ attn){
    __shared__ float Qs[32][33], Ks[32][33];
    int bg = blockIdx.x;
    int b = bg >> 1, g = bg & 1;
    size_t base = ((size_t)b*Cc + g*32) * HW;
    int chunk = HW / NSPLIT;           // 1024
    int nstart = blockIdx.y * chunk;
    int c = threadIdx.y, d = threadIdx.x;
    float acc = 0.f;
    for (int n0 = nstart; n0 < nstart + chunk; n0 += 32){
        Qs[threadIdx.y][threadIdx.x] = Q[base + (size_t)threadIdx.y*HW + n0 + threadIdx.x];
        Ks[threadIdx.y][threadIdx.x] = K[base + (size_t)threadIdx.y*HW + n0 + threadIdx.x];
        __syncthreads();
        #pragma unroll
        for (int nn=0;nn<32;nn++) acc += Qs[c][nn]*Ks[d][nn];
        __syncthreads();
    }
    atomicAdd(&attn[(bg*32 + c)*32 + d], acc);
}

// ---------------- softmax on attn, then M_b[o, g*32+d] = sum_c proj[o,g*32+c]*attn[c,d]
__global__ void softmax_M(const float* __restrict__ proj, const float* __restrict__ temp,
                          const float* __restrict__ attn,
                          const float* __restrict__ invQ, const float* __restrict__ invK,
                          float* __restrict__ M){
    __shared__ float at[32][33];
    int bg = blockIdx.x, b = bg >> 1, g = bg & 1;
    int t = threadIdx.x;
    int w = t >> 5, lane = t & 31;
    float v = attn[(bg*32 + w)*32 + lane]
            * invQ[b*Cc + g*32 + w] * invK[b*Cc + g*32 + lane] * temp[g];
    float m = v;
    #pragma unroll
    for (int o=16;o;o>>=1) m = fmaxf(m, __shfl_xor_sync(0xffffffffu, m, o));
    v = __expf(v - m);
    float s = v;
    #pragma unroll
    for (int o=16;o;o>>=1) s += __shfl_xor_sync(0xffffffffu, s, o);
    at[w][lane] = v / s;
    __syncthreads();
    int o0 = t >> 5;
    float m0 = 0.f, m1 = 0.f;
    #pragma unroll 4
    for (int c2=0;c2<32;c2++){
        float a = at[c2][lane];
        m0 += __ldg(&proj[o0*Cc       + g*32 + c2]) * a;
        m1 += __ldg(&proj[(o0+32)*Cc  + g*32 + c2]) * a;
    }
    M[((size_t)b*Cc + o0     )*Cc + g*32 + lane] = m0;
    M[((size_t)b*Cc + o0 + 32)*Cc + g*32 + lane] = m1;
}

// ============= line attention: row layout only, 1024 threads =============
// element (c,p) of line: base + c*HW + p, base = b*Cc*HW + line*Ww
#define QKS 200
#define VTS 68
#define STS_ 193
__global__ void __launch_bounds__(1024)
line_attn(const float* __restrict__ Q, const float* __restrict__ K,
          const float* __restrict__ V, const float* __restrict__ x1,
          float* __restrict__ out, const float* __restrict__ gamma_p){
    extern __shared__ float sm[];
    float* Qs = sm;                    // [64][200]
    float* Ks = Qs + 64*QKS;
    float* Vt = Ks + 64*QKS;           // transposed: Vt[p*68 + c]
    float* st = Vt + 192*VTS;          // score tile [64][193]
    int b = blockIdx.x / 192;
    int line = blockIdx.x - b*192;
    size_t base = (size_t)b*Cc*HW + (size_t)line*Ww;
    int t = threadIdx.x;

    for (int idx = t; idx < 64*192; idx += 1024){
        int c = idx / 192, p = idx - c*192;
        size_t ga = base + (size_t)c*HW + p;
        Qs[c*QKS+p] = Q[ga];
        Ks[c*QKS+p] = K[ga];
        st[c*STS_+p] = V[ga];
    }
    __syncthreads();
    for (int idx = t; idx < 64*192; idx += 1024){
        int c = idx & 63, p = idx >> 6;
        Vt[p*VTS + c] = st[c*STS_ + p];
    }
    float gamma = *gamma_p;
    __syncthreads();

    for (int i0 = 0; i0 < 192; i0 += 64){
        // --- score tile: thread = 1 row x 12 cols (3 chunks of 4) ---
        int ro = t >> 4;              // 0..63
        int jg = t & 15;
        u64c acc0[6];
        #pragma unroll
        for (int z=0;z<6;z++) acc0[z]=0ull;
        #pragma unroll 4
        for (int c=0;c<64;c++){
            float q0 = Qs[c*QKS + i0 + ro];
            u64c q0d = pack2(q0,q0);
            #pragma unroll
            for (int ch=0; ch<3; ch++){
                ulonglong2 kp = *(const ulonglong2*)(&Ks[c*QKS + jg*4 + ch*64]);
                acc0[2*ch  ] = ffma2(q0d, kp.x, acc0[2*ch  ]);
                acc0[2*ch+1] = ffma2(q0d, kp.y, acc0[2*ch+1]);
            }
        }
        #pragma unroll
        for (int ch=0; ch<3; ch++){
            #pragma unroll
            for (int p2=0;p2<2;p2++){
                float2 v0 = unpack2(acc0[2*ch+p2]);
                int col = jg*4 + ch*64 + p2*2;
                st[ro*STS_ + col]     = v0.x;
                st[ro*STS_ + col + 1] = v0.y;
            }
        }
        __syncthreads();
        // --- softmax per row: 32 warps x 2 rows ---
        int warp = t >> 5, lane = t & 31;
        #pragma unroll
        for (int rr=0;rr<2;rr++){
            int r = warp + rr*32;
            float vals[6]; float mx = -3.4e38f;
            #pragma unroll
            for (int e=0;e<6;e++){ vals[e] = st[r*STS_ + lane + e*32]; mx = fmaxf(mx, vals[e]); }
            #pragma unroll
            for (int o=16;o;o>>=1) mx = fmaxf(mx, __shfl_xor_sync(0xffffffffu, mx, o));
            float sme = 0.f;
            #pragma unroll
            for (int e=0;e<6;e++){ vals[e] = __expf(vals[e]-mx); sme += vals[e]; }
            #pragma unroll
            for (int o=16;o;o>>=1) sme += __shfl_xor_sync(0xffffffffu, sme, o);
            float inv = 1.f/sme;
            #pragma unroll
            for (int e=0;e<6;e++) st[r*STS_ + lane + e*32] = vals[e]*inv;
        }
        __syncthreads();
        // --- out: thread = 1 row x 4 channels (2 f32x2 pairs) ---
        int ro2 = t & 63;
        int c0 = (t >> 6) * 4;        // 0..60
        u64c oa0 = 0ull, oa1 = 0ull;
        const float* arow = st + ro2*STS_;
        #pragma unroll 4
        for (int j=0;j<192;j++){
            float a = arow[j];
            u64c ad = pack2(a,a);
            ulonglong2 v01 = *(const ulonglong2*)(&Vt[j*VTS + c0]);
            oa0 = ffma2(ad, v01.x, oa0);
            oa1 = ffma2(ad, v01.y, oa1);
        }
        int i = i0 + ro2;
        float res[4];
        { float2 v = unpack2(oa0); res[0]=v.x; res[1]=v.y; }
        { float2 v = unpack2(oa1); res[2]=v.x; res[3]=v.y; }
        #pragma unroll
        for (int k=0;k<4;k++){
            size_t ga = base + (size_t)(c0+k)*HW + i;
            out[ga] = gamma*res[k] + x1[ga];
        }
        __syncthreads();
    }
}

// ============= final: gelu( Wf [out1;out2;out3] + bf ), f32x2 =============
__global__ void __launch_bounds__(256, 2)
final_conv(const float* __restrict__ o1, const float* __restrict__ o2,
           const float* __restrict__ o3, const float* __restrict__ w,
           const float* __restrict__ bias, float* __restrict__ out){
    extern __shared__ u64c ws[];   // [192*64] u64 = 96KB
    for (int idx = threadIdx.x; idx < 192*64; idx += 256){
        int o = idx / 192, c = idx - o*192;
        float wv = w[idx];
        ws[c*64 + o] = pack2(wv, wv);
    }
    __syncthreads();
    int pg = threadIdx.x & 63, og = threadIdx.x >> 6;
    int blockPix = blockIdx.x * 256;
    int b = blockPix / HW;
    int n0 = blockPix - b*HW + pg*4;
    size_t boff = (size_t)b*Cc*HW + n0;
    u64c acc[16][2];
    #pragma unroll
    for (int i=0;i<16;i++){
        float bv = bias[og*16+i];
        u64c p = pack2(bv,bv);
        acc[i][0]=p; acc[i][1]=p;
    }
    const float* srcs[3] = {o1, o2, o3};
    #pragma unroll
    for (int s3=0;s3<3;s3++){
        const ulonglong2* pb = (const ulonglong2*)(srcs[s3] + boff);
        #pragma unroll 4
        for (int c=0;c<64;c++){
            ulonglong2 xv = pb[(size_t)c*CH_STRIDE_U2];
            const ulonglong2* wr = (const ulonglong2*)(ws + (s3*64+c)*64 + og*16);
            #pragma unroll
            for (int k=0;k<8;k++){
                ulonglong2 wp = wr[k];
                acc[2*k  ][0] = ffma2(wp.x, xv.x, acc[2*k  ][0]);
                acc[2*k  ][1] = ffma2(wp.x, xv.y, acc[2*k  ][1]);
                acc[2*k+1][0] = ffma2(wp.y, xv.x, acc[2*k+1][0]);
                acc[2*k+1][1] = ffma2(wp.y, xv.y, acc[2*k+1][1]);
            }
        }
    }
    float* yb = out + boff;
    #pragma unroll
    for (int i=0;i<16;i++){
        float2 a = unpack2(acc[i][0]);
        float2 bq = unpack2(acc[i][1]);
        float4 v;
        v.x = gelu_erf(a.x); v.y = gelu_erf(a.y);
        v.z = gelu_erf(bq.x); v.w = gelu_erf(bq.y);
        *((float4*)(yb + (size_t)(og*16+i)*HW)) = v;
    }
}

// =====================================================================
extern "C" void kernel_launch(void* const* d_in, const int* in_sizes, int n_in,
                              void* d_out, int out_size){
    (void)in_sizes; (void)n_in; (void)out_size;
    const float* x        = (const float*)d_in[0];
    const float* pw_w     = (const float*)d_in[1];
    const float* dw_w     = (const float*)d_in[2];
    const float* dw_b     = (const float*)d_in[3];
    const float* conv2_w  = (const float*)d_in[4];
    const float* conv2_b  = (const float*)d_in[5];
    const float* conv0_w  = (const float*)d_in[6];
    const float* conv0_b  = (const float*)d_in[7];
    const float* att_q_w  = (const float*)d_in[8];
    const float* att_k_w  = (const float*)d_in[9];
    const float* att_v_w  = (const float*)d_in[10];
    const float* att_p_w  = (const float*)d_in[11];
    const float* temp     = (const float*)d_in[12];
    const float* row_q_w  = (const float*)d_in[13];
    const float* row_k_w  = (const float*)d_in[14];
    const float* row_v_w  = (const float*)d_in[15];
    const float* row_g    = (const float*)d_in[16];
    const float* col_q_w  = (const float*)d_in[17];
    const float* col_k_w  = (const float*)d_in[18];
    const float* col_v_w  = (const float*)d_in[19];
    const float* col_g    = (const float*)d_in[20];
    const float* conv_w   = (const float*)d_in[21];
    const float* conv_b   = (const float*)d_in[22];
    float* out = (float*)d_out;

    float *A,*Bp,*Cp,*D,*E,*F,*G,*Hb,*invQ,*invK,*attn,*M;
    cudaGetSymbolAddress((void**)&A,    g_bufA);
    cudaGetSymbolAddress((void**)&Bp,   g_bufB);
    cudaGetSymbolAddress((void**)&Cp,   g_bufC);
    cudaGetSymbolAddress((void**)&D,    g_bufD);
    cudaGetSymbolAddress((void**)&E,    g_bufE);
    cudaGetSymbolAddress((void**)&F,    g_bufF);
    cudaGetSymbolAddress((void**)&G,    g_bufG);
    cudaGetSymbolAddress((void**)&Hb,   g_bufH);
    cudaGetSymbolAddress((void**)&invQ, g_invQ);
    cudaGetSymbolAddress((void**)&invK, g_invK);
    cudaGetSymbolAddress((void**)&attn, g_attn);
    cudaGetSymbolAddress((void**)&M,    g_M);

    const int LA_SMEM = (64*QKS + 64*QKS + 192*VTS + 64*STS_) * (int)sizeof(float); // 204032
    cudaFuncSetAttribute(line_attn, cudaFuncAttributeMaxDynamicSharedMemorySize, LA_SMEM);
    const int XF_SMEM = 2*4096*(int)sizeof(u64c);   // 65536
    cudaFuncSetAttribute(x1_fuse, cudaFuncAttributeMaxDynamicSharedMemorySize, XF_SMEM);
    const int FC_SMEM = 192*64*(int)sizeof(u64c);   // 98304
    cudaFuncSetAttribute(final_conv, cudaFuncAttributeMaxDynamicSharedMemorySize, FC_SMEM);

    const int PBLK = 256;
    const int CGRD = NPIX / 128;    // 1152 (conv1x1 tiles of 128 px)
    const int PGRD = NPIX / PBLK;   // 576  (x1_fuse / final_conv tiles of 256 px)
    const dim3 TGRD(Bb*Cc, 36);     // transpose tiles

    // ---- x1 = conv2(gelu(dw(pw(x)))) + conv0(x) ----
    conv1x1_nb<<<CGRD, PBLK>>>(x, pw_w, A);
    dwconv<<<NTOT/256, 256>>>(A, dw_w, dw_b, Bp);      // emits gelu(dw out)
    x1_fuse<<<PGRD, PBLK, XF_SMEM>>>(Bp, x, conv2_w, conv2_b, conv0_w, conv0_b, Cp);

    // ---- channel attention -> out1 (E) ----
    conv1x1_nb<<<CGRD, PBLK>>>(Cp, att_q_w, A);
    conv1x1_nb<<<CGRD, PBLK>>>(Cp, att_k_w, Bp);
    conv1x1_nb<<<CGRD, PBLK>>>(Cp, att_v_w, D);
    norm_kernel<<<dim3(Bb*Cc, 2), 256>>>(A, Bp, invQ, invK);
    zero_attn<<<(Bb*HEADS*32*32 + 255)/256, 256>>>(attn);
    attn_dot<<<dim3(Bb*HEADS, NSPLIT), dim3(32,32)>>>(A, Bp, attn);
    softmax_M<<<Bb*HEADS, 1024>>>(att_p_w, temp, attn, invQ, invK, M);
    conv1x1_batch<<<CGRD, PBLK>>>(D, M, E);

    // ---- row attention -> out2 (F) ----
    conv1x1_nb<<<CGRD, PBLK>>>(Cp, row_q_w, A);
    conv1x1_nb<<<CGRD, PBLK>>>(Cp, row_k_w, Bp);
    conv1x1_nb<<<CGRD, PBLK>>>(E,  row_v_w, D);
    line_attn<<<Bb*Hh, 1024, LA_SMEM>>>(A, Bp, D, Cp, F, row_g);

    // ---- col attention -> out3 (G), computed in transposed space ----
    transpose_hw<<<TGRD, 256>>>(Cp, G);    // G  = x1^T
    transpose_hw<<<TGRD, 256>>>(E,  Hb);   // Hb = out1^T
    conv1x1_nb<<<CGRD, PBLK>>>(G,  col_q_w, A);
    conv1x1_nb<<<CGRD, PBLK>>>(G,  col_k_w, Bp);
    conv1x1_nb<<<CGRD, PBLK>>>(Hb, col_v_w, D);
    line_attn<<<Bb*Ww, 1024, LA_SMEM>>>(A, Bp, D, G, Hb, col_g);  // Hb = out3^T
    transpose_hw<<<TGRD, 256>>>(Hb, G);    // G = out3

    // ---- fuse + gelu ----
    final_conv<<<PGRD, PBLK, FC_SMEM>>>(E, F, G, conv_w, conv_b, out);
}